// round 15
// baseline (speedup 1.0000x reference)
#include <cuda_runtime.h>
#include <cuda_fp16.h>
#include <cstdint>

// ViT patch embedding, fp16 mma.sync m16n8k16 (f32 acc).
// R14: patchify fused via cp.async f32 staging ring (NO register staging):
//   images --cp.async--> smem f32 (2 stages) --LDS/cvt/STS (self-owned)--> f16 A (2 stages)
//   W fp16 via tiny prepass; B via 3-stage cp.async ring. 1 syncthreads/iter.
// GEMM: block 128x256, BK=64, warp tile 64x64, 256 thr, 1 blk/SM, ldmatrix.x4.

#define NPATCH  196
#define NIMG    128
#define KDIM    768
#define NDIM    768
#define MTOT    25088

#define BM 128
#define BN 256
#define BK 64
#define NITER (KDIM / BK)              // 12
#define AROW_B 128                     // f16 A row bytes
#define A16_OFF 0
#define A16_ST  16384                  // 128 rows x 128B
#define B_OFF   32768
#define B_ST    32768                  // 256 rows x 128B
#define A32_OFF 131072
#define A32_ST  32768                  // 128 rows x 256B (64 f32)
#define SMEM_BYTES 196608              // 192KB

__device__ __half W_h[(size_t)NDIM * KDIM];     // 1.18 MB

__device__ __forceinline__ void mma_f16(float* c, const uint32_t* a, const uint32_t* b) {
    asm volatile(
        "mma.sync.aligned.m16n8k16.row.col.f32.f16.f16.f32 "
        "{%0,%1,%2,%3}, {%4,%5,%6,%7}, {%8,%9}, {%0,%1,%2,%3};\n"
        : "+f"(c[0]), "+f"(c[1]), "+f"(c[2]), "+f"(c[3])
        : "r"(a[0]), "r"(a[1]), "r"(a[2]), "r"(a[3]), "r"(b[0]), "r"(b[1]));
}
__device__ __forceinline__ void ldsm4(uint32_t* r, uint32_t addr) {
    asm volatile("ldmatrix.sync.aligned.m8n8.x4.shared.b16 {%0,%1,%2,%3}, [%4];"
                 : "=r"(r[0]), "=r"(r[1]), "=r"(r[2]), "=r"(r[3]) : "r"(addr));
}
__device__ __forceinline__ void cp16(uint32_t s, const void* g) {
    asm volatile("cp.async.cg.shared.global [%0], [%1], 16;\n" :: "r"(s), "l"(g));
}
__device__ __forceinline__ void cp_commit() { asm volatile("cp.async.commit_group;\n"); }
template <int N>
__device__ __forceinline__ void cp_wait() { asm volatile("cp.async.wait_group %0;\n" :: "n"(N)); }

// ---------------- prepass: W -> fp16 (warp/row) + CLS rows ----------------
__global__ __launch_bounds__(256) void prepass_w(const float* __restrict__ W,
                                                 const float* __restrict__ cls,
                                                 float* __restrict__ out) {
    const int n    = blockIdx.x * 8 + (threadIdx.x >> 5);   // 96 blocks -> 768 rows
    const int lane = threadIdx.x & 31;
    const float* src = W + (size_t)n * KDIM + lane * 8;
    __half* dst = W_h + (size_t)n * KDIM + lane * 8;
    #pragma unroll
    for (int p = 0; p < 3; ++p) {
        const float4 v0 = *reinterpret_cast<const float4*>(src + p * 256);
        const float4 v1 = *reinterpret_cast<const float4*>(src + p * 256 + 4);
        __half2 h[4];
        h[0] = __floats2half2_rn(v0.x, v0.y);
        h[1] = __floats2half2_rn(v0.z, v0.w);
        h[2] = __floats2half2_rn(v1.x, v1.y);
        h[3] = __floats2half2_rn(v1.z, v1.w);
        *reinterpret_cast<uint4*>(dst + p * 256) = *reinterpret_cast<uint4*>(h);
    }
    // CLS: 128 imgs x 192 float4 = 24576 = 96 blocks x 256 threads
    const int i   = blockIdx.x * 256 + threadIdx.x;
    const int img = i / 192, n4 = i - img * 192;
    reinterpret_cast<float4*>(out + (size_t)img * 197 * NDIM)[n4] =
        reinterpret_cast<const float4*>(cls)[n4];
}

// ---------------- main GEMM ----------------
__global__ __launch_bounds__(256, 1) void vit_gemm(
    const float* __restrict__ images,
    const float* __restrict__ bias,
    float* __restrict__ out)
{
    extern __shared__ __align__(16) char smc[];

    const int tid  = threadIdx.x;
    const int lane = tid & 31;
    const int warp = tid >> 5;          // 0..7
    const int wm   = warp & 1;          // 2 m-positions of 64
    const int wn   = warp >> 1;         // 4 n-positions of 64
    const int g    = lane >> 2;         // 0..7
    const int tg   = lane & 3;          // 0..3

    const int bm = blockIdx.y * BM;
    const int bn = blockIdx.x * BN;

    const uint32_t sbase = (uint32_t)__cvta_generic_to_shared(smc);

    // ---------------- B loader (quarter-warp = one 128B row) ----------------
    const int lq = lane >> 3;
    const int lc = lane & 7;
    const uint32_t x_even = (uint32_t)((lc ^ lq) << 4);
    const uint32_t x_odd  = (uint32_t)((lc ^ (lq + 4)) << 4);
    const __half* bsrc = W_h + (size_t)(bn + 32 * warp + lq) * KDIM + lc * 8;
    const uint32_t sts_b0 = (uint32_t)(32 * warp + lq) * AROW_B;

    auto loadB = [&](int it) {
        const int s3 = it - (it / 3) * 3;
        const int k0 = it * BK;
        const uint32_t sb0 = sbase + B_OFF + (uint32_t)s3 * B_ST + sts_b0;
        #pragma unroll
        for (int i = 0; i < 8; ++i)
            cp16(sb0 + i * 512u + ((i & 1) ? x_odd : x_even),
                 bsrc + (size_t)i * (4 * KDIM) + k0);
    };

    // ---------------- A f32 loader + converter (thread-owned 128B) -----------
    const int r = tid & 127;            // A row
    const int h = tid >> 7;             // k-half (32 floats)
    const int m0   = bm + r;
    const int img0 = m0 / NPATCH;
    const int pch0 = m0 - img0 * NPATCH;
    const int Pi0  = pch0 / 14;
    const int Pj0  = pch0 - Pi0 * 14;
    const float* abase = images + (size_t)img0 * 150528 + (size_t)(Pi0 * 16) * 224 + Pj0 * 16;
    const int rx15 = r & 15;
    const int rx7  = r & 7;

    auto loadA32 = [&](int it) {
        const int s2 = it & 1;
        const uint32_t dst = sbase + A32_OFF + (uint32_t)s2 * A32_ST + (uint32_t)r * 256u;
        const float* src = abase + (size_t)(it >> 2) * 50176
                         + (size_t)((it & 3) * 4 + 2 * h) * 224;
        #pragma unroll
        for (int d = 0; d < 2; ++d)
            #pragma unroll
            for (int q = 0; q < 4; ++q)
                cp16(dst + (uint32_t)((h * 8 + d * 4 + q) ^ rx15) * 16u,
                     src + d * 224 + q * 4);
    };

    auto convertZ = [&](int jt, int z0) {   // converts f32(jt) units z0,z0+1 -> f16(jt)
        const int s = jt & 1;
        const char* srcb = smc + A32_OFF + (size_t)s * A32_ST + (size_t)r * 256;
        char* dstb = smc + A16_OFF + (size_t)s * A16_ST + (size_t)r * 128;
        #pragma unroll
        for (int z = z0; z < z0 + 2; ++z) {
            const float4 u0 = *reinterpret_cast<const float4*>(
                srcb + (size_t)((h * 8 + 2 * z)     ^ rx15) * 16);
            const float4 u1 = *reinterpret_cast<const float4*>(
                srcb + (size_t)((h * 8 + 2 * z + 1) ^ rx15) * 16);
            __half2 hh[4];
            hh[0] = __floats2half2_rn(u0.x, u0.y);
            hh[1] = __floats2half2_rn(u0.z, u0.w);
            hh[2] = __floats2half2_rn(u1.x, u1.y);
            hh[3] = __floats2half2_rn(u1.z, u1.w);
            *reinterpret_cast<uint4*>(dstb + (size_t)(((4 * h + z) ^ rx7) << 4)) =
                *reinterpret_cast<uint4*>(hh);
        }
    };

    float acc[4][8][4];
    #pragma unroll
    for (int mt = 0; mt < 4; ++mt)
        #pragma unroll
        for (int nt = 0; nt < 8; ++nt)
            #pragma unroll
            for (int rr = 0; rr < 4; ++rr) acc[mt][nt][rr] = 0.f;

    // prologue
    loadA32(0); loadB(0); cp_commit();
    loadA32(1); loadB(1); cp_commit();
    cp_wait<1>();                        // group0 (A32(0), B(0)) done
    convertZ(0, 0); convertZ(0, 2);      // f16 stage0 ready (self-owned data)

    // ---------------- ldmatrix lane constants ----------------
    const int a_sub = (lane & 7) + ((lane >> 3) & 1) * 8;
    const int chA   = (lane >> 4) & 1;
    const int b_sub = (lane & 7) + ((lane >> 4) & 1) * 8;
    const int chB   = (lane >> 3) & 1;
    const uint32_t lx = (uint32_t)(lane & 7);
    const uint32_t aRel = (uint32_t)(wm * 64 + a_sub) * AROW_B;
    const uint32_t bRel = (uint32_t)(wn * 64 + b_sub) * AROW_B;

    for (int it = 0; it < NITER; ++it) {
        cp_wait<0>();                    // prefetch distance = 1 iter >> latency
        __syncthreads();

        const uint32_t stA = sbase + A16_OFF + (uint32_t)(it & 1) * A16_ST + aRel;
        const int s3 = it - (it / 3) * 3;
        const uint32_t stB = sbase + B_OFF + (uint32_t)s3 * B_ST + bRel;
        const bool pf2 = (it + 2 < NITER);
        const bool cvt = (it + 1 < NITER);

        #pragma unroll
        for (int ks = 0; ks < 4; ++ks) {
            uint32_t af[4][4], bf[4][4];
            const uint32_t ach = ((uint32_t)(2 * ks + chA) ^ lx) << 4;
            const uint32_t bch = ((uint32_t)(2 * ks + chB) ^ lx) << 4;
            #pragma unroll
            for (int mt = 0; mt < 4; ++mt)
                ldsm4(af[mt], stA + mt * 2048u + ach);
            #pragma unroll
            for (int p = 0; p < 4; ++p)
                ldsm4(bf[p], stB + p * 2048u + bch);

            #pragma unroll
            for (int mt = 0; mt < 4; ++mt)
                #pragma unroll
                for (int nt = 0; nt < 8; ++nt)
                    mma_f16(acc[mt][nt], af[mt], &bf[nt >> 1][(nt & 1) * 2]);

            if (ks == 0) {
                if (pf2) { loadA32(it + 2); loadB(it + 2); cp_commit(); }
                if (cvt) convertZ(it + 1, 0);
            } else if (ks == 1) {
                if (cvt) convertZ(it + 1, 2);
            }
        }
    }

    // ---------------- epilogue: bias + scatter ----------------
    float bv[8][2];
    #pragma unroll
    for (int nt = 0; nt < 8; ++nt) {
        const int col = bn + wn * 64 + nt * 8 + tg * 2;
        bv[nt][0] = bias[col];
        bv[nt][1] = bias[col + 1];
    }

    #pragma unroll
    for (int mt = 0; mt < 4; ++mt) {
        #pragma unroll
        for (int rh = 0; rh < 2; ++rh) {
            const int m     = bm + wm * 64 + mt * 16 + rh * 8 + g;
            const int img   = m / NPATCH;
            const int patch = m - img * NPATCH;
            float* orow = out + ((size_t)img * 197 + patch + 1) * NDIM;
            #pragma unroll
            for (int nt = 0; nt < 8; ++nt) {
                const int col = bn + wn * 64 + nt * 8 + tg * 2;
                float2 v;
                v.x = acc[mt][nt][rh * 2 + 0] + bv[nt][0];
                v.y = acc[mt][nt][rh * 2 + 1] + bv[nt][1];
                *reinterpret_cast<float2*>(orow + col) = v;
            }
        }
    }
}

extern "C" void kernel_launch(void* const* d_in, const int* in_sizes, int n_in,
                              void* d_out, int out_size) {
    const float* images = (const float*)d_in[0];
    const float* W      = (const float*)d_in[1];
    const float* b      = (const float*)d_in[2];
    const float* cls    = (const float*)d_in[3];
    float* out          = (float*)d_out;

    cudaFuncSetAttribute(vit_gemm, cudaFuncAttributeMaxDynamicSharedMemorySize, SMEM_BYTES);

    prepass_w<<<96, 256>>>(W, cls, out);
    dim3 grid(NDIM / BN, MTOT / BM);   // (3, 196): the 3 A-sharers run concurrently (L2 reuse)
    vit_gemm<<<grid, 256, SMEM_BYTES>>>(images, b, out);
}

// round 16
// speedup vs baseline: 1.0614x; 1.0614x over previous
#include <cuda_runtime.h>
#include <cuda_fp16.h>
#include <cstdint>

// ViT patch embedding, fp16 mma.sync m16n8k16 (f32 acc).
// R15: fused patchify, attempt 3 — distance-2 pipeline restored:
//   two commit groups/iter (B @ks0, A32 @ks1, committed even when empty),
//   cp_wait<2> at iter top; rings B mod3, A32 mod3 (self-owned rows), A16 x2.
// GEMM: block 128x256, BK=64, warp tile 64x64, 256 thr, 1 blk/SM, ldmatrix.x4.

#define NPATCH  196
#define NIMG    128
#define KDIM    768
#define NDIM    768
#define MTOT    25088

#define BM 128
#define BN 256
#define BK 64
#define NITER (KDIM / BK)              // 12
#define AROW_B 128                     // f16 A row bytes
#define A16_OFF 0                      // 2 x 16KB
#define A16_ST  16384
#define B_OFF   32768                  // 3 x 32KB
#define B_ST    32768
#define A32_OFF 131072                 // 3 x 32KB
#define A32_ST  32768
#define SMEM_BYTES 229376              // 224KB

__device__ __half W_h[(size_t)NDIM * KDIM];

__device__ __forceinline__ void mma_f16(float* c, const uint32_t* a, const uint32_t* b) {
    asm volatile(
        "mma.sync.aligned.m16n8k16.row.col.f32.f16.f16.f32 "
        "{%0,%1,%2,%3}, {%4,%5,%6,%7}, {%8,%9}, {%0,%1,%2,%3};\n"
        : "+f"(c[0]), "+f"(c[1]), "+f"(c[2]), "+f"(c[3])
        : "r"(a[0]), "r"(a[1]), "r"(a[2]), "r"(a[3]), "r"(b[0]), "r"(b[1]));
}
__device__ __forceinline__ void ldsm4(uint32_t* r, uint32_t addr) {
    asm volatile("ldmatrix.sync.aligned.m8n8.x4.shared.b16 {%0,%1,%2,%3}, [%4];"
                 : "=r"(r[0]), "=r"(r[1]), "=r"(r[2]), "=r"(r[3]) : "r"(addr));
}
__device__ __forceinline__ void cp16(uint32_t s, const void* g) {
    asm volatile("cp.async.cg.shared.global [%0], [%1], 16;\n" :: "r"(s), "l"(g));
}
__device__ __forceinline__ void cp_commit() { asm volatile("cp.async.commit_group;\n"); }
template <int N>
__device__ __forceinline__ void cp_wait() { asm volatile("cp.async.wait_group %0;\n" :: "n"(N)); }

// ---------------- prepass: W -> fp16 (warp/row) + CLS rows ----------------
__global__ __launch_bounds__(256) void prepass_w(const float* __restrict__ W,
                                                 const float* __restrict__ cls,
                                                 float* __restrict__ out) {
    const int n    = blockIdx.x * 8 + (threadIdx.x >> 5);
    const int lane = threadIdx.x & 31;
    const float* src = W + (size_t)n * KDIM + lane * 8;
    __half* dst = W_h + (size_t)n * KDIM + lane * 8;
    #pragma unroll
    for (int p = 0; p < 3; ++p) {
        const float4 v0 = *reinterpret_cast<const float4*>(src + p * 256);
        const float4 v1 = *reinterpret_cast<const float4*>(src + p * 256 + 4);
        __half2 h[4];
        h[0] = __floats2half2_rn(v0.x, v0.y);
        h[1] = __floats2half2_rn(v0.z, v0.w);
        h[2] = __floats2half2_rn(v1.x, v1.y);
        h[3] = __floats2half2_rn(v1.z, v1.w);
        *reinterpret_cast<uint4*>(dst + p * 256) = *reinterpret_cast<uint4*>(h);
    }
    const int i   = blockIdx.x * 256 + threadIdx.x;
    const int img = i / 192, n4 = i - img * 192;
    reinterpret_cast<float4*>(out + (size_t)img * 197 * NDIM)[n4] =
        reinterpret_cast<const float4*>(cls)[n4];
}

// ---------------- main GEMM ----------------
__global__ __launch_bounds__(256, 1) void vit_gemm(
    const float* __restrict__ images,
    const float* __restrict__ bias,
    float* __restrict__ out)
{
    extern __shared__ __align__(16) char smc[];

    const int tid  = threadIdx.x;
    const int lane = tid & 31;
    const int warp = tid >> 5;          // 0..7
    const int wm   = warp & 1;
    const int wn   = warp >> 1;
    const int g    = lane >> 2;
    const int tg   = lane & 3;

    const int bm = blockIdx.y * BM;
    const int bn = blockIdx.x * BN;

    const uint32_t sbase = (uint32_t)__cvta_generic_to_shared(smc);

    // ---------------- B loader ----------------
    const int lq = lane >> 3;
    const int lc = lane & 7;
    const uint32_t x_even = (uint32_t)((lc ^ lq) << 4);
    const uint32_t x_odd  = (uint32_t)((lc ^ (lq + 4)) << 4);
    const __half* bsrc = W_h + (size_t)(bn + 32 * warp + lq) * KDIM + lc * 8;
    const uint32_t sts_b0 = (uint32_t)(32 * warp + lq) * AROW_B;

    auto loadB = [&](int it) {
        if (it < NITER) {
            const int s3 = it - (it / 3) * 3;
            const int k0 = it * BK;
            const uint32_t sb0 = sbase + B_OFF + (uint32_t)s3 * B_ST + sts_b0;
            #pragma unroll
            for (int i = 0; i < 8; ++i)
                cp16(sb0 + i * 512u + ((i & 1) ? x_odd : x_even),
                     bsrc + (size_t)i * (4 * KDIM) + k0);
        }
        cp_commit();                    // commit even when empty (wait arithmetic)
    };

    // ---------------- A f32 loader + converter (thread-owned rows) -----------
    const int r = tid & 127;
    const int h = tid >> 7;
    const int m0   = bm + r;
    const int img0 = m0 / NPATCH;
    const int pch0 = m0 - img0 * NPATCH;
    const int Pi0  = pch0 / 14;
    const int Pj0  = pch0 - Pi0 * 14;
    const float* abase = images + (size_t)img0 * 150528 + (size_t)(Pi0 * 16) * 224 + Pj0 * 16;
    const int rx15 = r & 15;
    const int rx7  = r & 7;

    auto loadA32 = [&](int it) {
        if (it < NITER) {
            const int s3 = it - (it / 3) * 3;
            const uint32_t dst = sbase + A32_OFF + (uint32_t)s3 * A32_ST + (uint32_t)r * 256u;
            const float* src = abase + (size_t)(it >> 2) * 50176
                             + (size_t)((it & 3) * 4 + 2 * h) * 224;
            #pragma unroll
            for (int d = 0; d < 2; ++d)
                #pragma unroll
                for (int q = 0; q < 4; ++q)
                    cp16(dst + (uint32_t)((h * 8 + d * 4 + q) ^ rx15) * 16u,
                         src + d * 224 + q * 4);
        }
        cp_commit();
    };

    auto convertZ = [&](int jt, int z0) {   // A32(jt) units z0,z0+1 -> A16(jt)
        const int s3 = jt - (jt / 3) * 3;
        const char* srcb = smc + A32_OFF + (size_t)s3 * A32_ST + (size_t)r * 256;
        char* dstb = smc + A16_OFF + (size_t)(jt & 1) * A16_ST + (size_t)r * 128;
        #pragma unroll
        for (int z = z0; z < z0 + 2; ++z) {
            const float4 u0 = *reinterpret_cast<const float4*>(
                srcb + (size_t)((h * 8 + 2 * z)     ^ rx15) * 16);
            const float4 u1 = *reinterpret_cast<const float4*>(
                srcb + (size_t)((h * 8 + 2 * z + 1) ^ rx15) * 16);
            __half2 hh[4];
            hh[0] = __floats2half2_rn(u0.x, u0.y);
            hh[1] = __floats2half2_rn(u0.z, u0.w);
            hh[2] = __floats2half2_rn(u1.x, u1.y);
            hh[3] = __floats2half2_rn(u1.z, u1.w);
            *reinterpret_cast<uint4*>(dstb + (size_t)(((4 * h + z) ^ rx7) << 4)) =
                *reinterpret_cast<uint4*>(hh);
        }
    };

    float acc[4][8][4];
    #pragma unroll
    for (int mt = 0; mt < 4; ++mt)
        #pragma unroll
        for (int nt = 0; nt < 8; ++nt)
            #pragma unroll
            for (int rr = 0; rr < 4; ++rr) acc[mt][nt][rr] = 0.f;

    // prologue: G1={A32(0),A32(1),B(0)}  G2={B(1)}  G3={A32(2)}
    {
        if (0 < NITER) { /* keep commit structure explicit */ }
        // G1
        {
            const int s0 = 0;
            (void)s0;
        }
        // inline loads without the auto-commit lambdas for G1 packing:
        // A32(0), A32(1), B(0) in one group
        {
            // A32(0)
            const uint32_t dst0 = sbase + A32_OFF + 0u * A32_ST + (uint32_t)r * 256u;
            const float* src0 = abase + (size_t)0 * 50176 + (size_t)(0 * 4 + 2 * h) * 224;
            #pragma unroll
            for (int d = 0; d < 2; ++d)
                #pragma unroll
                for (int q = 0; q < 4; ++q)
                    cp16(dst0 + (uint32_t)((h * 8 + d * 4 + q) ^ rx15) * 16u,
                         src0 + d * 224 + q * 4);
            // A32(1)
            const uint32_t dst1 = sbase + A32_OFF + 1u * A32_ST + (uint32_t)r * 256u;
            const float* src1 = abase + (size_t)(1 * 4 + 2 * h) * 224;   // it=1: ch0, rows 4..
            #pragma unroll
            for (int d = 0; d < 2; ++d)
                #pragma unroll
                for (int q = 0; q < 4; ++q)
                    cp16(dst1 + (uint32_t)((h * 8 + d * 4 + q) ^ rx15) * 16u,
                         src1 + d * 224 + q * 4);
            // B(0)
            const uint32_t sb0 = sbase + B_OFF + sts_b0;
            #pragma unroll
            for (int i = 0; i < 8; ++i)
                cp16(sb0 + i * 512u + ((i & 1) ? x_odd : x_even),
                     bsrc + (size_t)i * (4 * KDIM));
            cp_commit();
        }
        loadB(1);        // G2
        loadA32(2);      // G3
        cp_wait<2>();    // G1 done: A32(0), A32(1), B(0)
        convertZ(0, 0); convertZ(0, 2);
    }

    // ---------------- ldmatrix lane constants ----------------
    const int a_sub = (lane & 7) + ((lane >> 3) & 1) * 8;
    const int chA   = (lane >> 4) & 1;
    const int b_sub = (lane & 7) + ((lane >> 4) & 1) * 8;
    const int chB   = (lane >> 3) & 1;
    const uint32_t lx = (uint32_t)(lane & 7);
    const uint32_t aRel = (uint32_t)(wm * 64 + a_sub) * AROW_B;
    const uint32_t bRel = (uint32_t)(wn * 64 + b_sub) * AROW_B;

    for (int it = 0; it < NITER; ++it) {
        cp_wait<2>();                    // drains B(it) and A32(it+1)
        __syncthreads();

        const uint32_t stA = sbase + A16_OFF + (uint32_t)(it & 1) * A16_ST + aRel;
        const int s3 = it - (it / 3) * 3;
        const uint32_t stB = sbase + B_OFF + (uint32_t)s3 * B_ST + bRel;
        const bool cvt = (it + 1 < NITER);

        #pragma unroll
        for (int ks = 0; ks < 4; ++ks) {
            uint32_t af[4][4], bf[4][4];
            const uint32_t ach = ((uint32_t)(2 * ks + chA) ^ lx) << 4;
            const uint32_t bch = ((uint32_t)(2 * ks + chB) ^ lx) << 4;
            #pragma unroll
            for (int mt = 0; mt < 4; ++mt)
                ldsm4(af[mt], stA + mt * 2048u + ach);
            #pragma unroll
            for (int p = 0; p < 4; ++p)
                ldsm4(bf[p], stB + p * 2048u + bch);

            #pragma unroll
            for (int mt = 0; mt < 4; ++mt)
                #pragma unroll
                for (int nt = 0; nt < 8; ++nt)
                    mma_f16(acc[mt][nt], af[mt], &bf[nt >> 1][(nt & 1) * 2]);

            if (ks == 0) {
                loadB(it + 2);                    // commit GB (maybe empty)
                if (cvt) convertZ(it + 1, 0);
            } else if (ks == 1) {
                loadA32(it + 3);                  // commit GA (maybe empty)
                if (cvt) convertZ(it + 1, 2);
            }
        }
    }
    cp_wait<0>();

    // ---------------- epilogue: bias + scatter ----------------
    float bv[8][2];
    #pragma unroll
    for (int nt = 0; nt < 8; ++nt) {
        const int col = bn + wn * 64 + nt * 8 + tg * 2;
        bv[nt][0] = bias[col];
        bv[nt][1] = bias[col + 1];
    }

    #pragma unroll
    for (int mt = 0; mt < 4; ++mt) {
        #pragma unroll
        for (int rh = 0; rh < 2; ++rh) {
            const int m     = bm + wm * 64 + mt * 16 + rh * 8 + g;
            const int img   = m / NPATCH;
            const int patch = m - img * NPATCH;
            float* orow = out + ((size_t)img * 197 + patch + 1) * NDIM;
            #pragma unroll
            for (int nt = 0; nt < 8; ++nt) {
                const int col = bn + wn * 64 + nt * 8 + tg * 2;
                float2 v;
                v.x = acc[mt][nt][rh * 2 + 0] + bv[nt][0];
                v.y = acc[mt][nt][rh * 2 + 1] + bv[nt][1];
                *reinterpret_cast<float2*>(orow + col) = v;
            }
        }
    }
}

extern "C" void kernel_launch(void* const* d_in, const int* in_sizes, int n_in,
                              void* d_out, int out_size) {
    const float* images = (const float*)d_in[0];
    const float* W      = (const float*)d_in[1];
    const float* b      = (const float*)d_in[2];
    const float* cls    = (const float*)d_in[3];
    float* out          = (float*)d_out;

    cudaFuncSetAttribute(vit_gemm, cudaFuncAttributeMaxDynamicSharedMemorySize, SMEM_BYTES);

    prepass_w<<<96, 256>>>(W, cls, out);
    dim3 grid(NDIM / BN, MTOT / BM);   // (3, 196): A-sharers concurrent (L2 reuse)
    vit_gemm<<<grid, 256, SMEM_BYTES>>>(images, b, out);
}

// round 17
// speedup vs baseline: 1.3281x; 1.2513x over previous
#include <cuda_runtime.h>
#include <cuda_fp16.h>
#include <cstdint>

// ViT patch embedding, fp16 mma.sync m16n8k16 (f32 acc).
// R16: consolidation. GEMM = R9's exact best (86.5us): block 128x256, BK=64,
// warp tile 64x64, 256 thr, 1 blk/SM, 3-stage cp.async ring, ldmatrix.x4,
// canonical 128B XOR swizzle. ONE unified prepass (images->A_pre fp16 with
// __ldcs, W->W_h fp16, CLS rows). Fusion abandoned (3 attempts, all cost
// more than the prepass they save).

#define NPATCH  196
#define NIMG    128
#define KDIM    768
#define NDIM    768
#define MTOT    25088

#define BM 128
#define BN 256
#define BK 64
#define NITER (KDIM / BK)              // 12
#define AROW_B 128                     // bytes per row (64 halves)
#define ASTAGE_B (BM * AROW_B)         // 16384
#define BSTAGE_B (BN * AROW_B)         // 32768
#define STAGE_BYTES (ASTAGE_B + BSTAGE_B)   // 49152
#define NSTG 3
#define SMEM_BYTES (NSTG * STAGE_BYTES)     // 147456

__device__ __half A_pre[(size_t)MTOT * KDIM];   // 38.5 MB (fits L2)
__device__ __half W_h[(size_t)NDIM * KDIM];     // 1.18 MB

__device__ __forceinline__ void mma_f16(float* c, const uint32_t* a, const uint32_t* b) {
    asm volatile(
        "mma.sync.aligned.m16n8k16.row.col.f32.f16.f16.f32 "
        "{%0,%1,%2,%3}, {%4,%5,%6,%7}, {%8,%9}, {%0,%1,%2,%3};\n"
        : "+f"(c[0]), "+f"(c[1]), "+f"(c[2]), "+f"(c[3])
        : "r"(a[0]), "r"(a[1]), "r"(a[2]), "r"(a[3]), "r"(b[0]), "r"(b[1]));
}
__device__ __forceinline__ void ldsm4(uint32_t* r, uint32_t addr) {
    asm volatile("ldmatrix.sync.aligned.m8n8.x4.shared.b16 {%0,%1,%2,%3}, [%4];"
                 : "=r"(r[0]), "=r"(r[1]), "=r"(r[2]), "=r"(r[3]) : "r"(addr));
}
__device__ __forceinline__ void cp16(uint32_t s, const void* g) {
    asm volatile("cp.async.cg.shared.global [%0], [%1], 16;\n" :: "r"(s), "l"(g));
}
__device__ __forceinline__ void cp_commit() { asm volatile("cp.async.commit_group;\n"); }
template <int N>
__device__ __forceinline__ void cp_wait() { asm volatile("cp.async.wait_group %0;\n" :: "n"(N)); }

__device__ __forceinline__ float4 ldcs4(const float* p) {
    float4 v;
    asm volatile("ld.global.cs.v4.f32 {%0,%1,%2,%3}, [%4];"
                 : "=f"(v.x), "=f"(v.y), "=f"(v.z), "=f"(v.w) : "l"(p));
    return v;
}

// ---------------- unified prepass ----------------
// warp-per-patch: images -> A_pre (fp16, evict-first reads);
// warp-per-row:   W -> W_h;  CLS rows on first 96 blocks.
#define PRE_BLOCKS ((MTOT + NDIM) / 8)          // 3232

__global__ __launch_bounds__(256) void prepass(const float* __restrict__ images,
                                               const float* __restrict__ W,
                                               const float* __restrict__ cls,
                                               float* __restrict__ out) {
    const int wg   = blockIdx.x * 8 + (threadIdx.x >> 5);
    const int lane = threadIdx.x & 31;
    if (wg < MTOT) {
        const int m   = wg;
        const int img = m / NPATCH, pch = m - img * NPATCH;
        const int Pi  = pch / 14,   Pj  = pch - Pi * 14;
        // k = p*256 + lane*8 -> c=p, ph=lane>>1, pw=(lane&1)*8
        const float* src = images + (size_t)img * 150528
                         + (size_t)(Pi * 16 + (lane >> 1)) * 224 + Pj * 16 + (lane & 1) * 8;
        __half* dst = A_pre + (size_t)m * KDIM + lane * 8;
        #pragma unroll
        for (int p = 0; p < 3; ++p) {
            const float4 v0 = ldcs4(src + (size_t)p * 50176);
            const float4 v1 = ldcs4(src + (size_t)p * 50176 + 4);
            __half2 h[4];
            h[0] = __floats2half2_rn(v0.x, v0.y);
            h[1] = __floats2half2_rn(v0.z, v0.w);
            h[2] = __floats2half2_rn(v1.x, v1.y);
            h[3] = __floats2half2_rn(v1.z, v1.w);
            *reinterpret_cast<uint4*>(dst + p * 256) = *reinterpret_cast<uint4*>(h);
        }
    } else if (wg < MTOT + NDIM) {
        const int n = wg - MTOT;
        const float* src = W + (size_t)n * KDIM + lane * 8;
        __half* dst = W_h + (size_t)n * KDIM + lane * 8;
        #pragma unroll
        for (int p = 0; p < 3; ++p) {
            const float4 v0 = *reinterpret_cast<const float4*>(src + p * 256);
            const float4 v1 = *reinterpret_cast<const float4*>(src + p * 256 + 4);
            __half2 h[4];
            h[0] = __floats2half2_rn(v0.x, v0.y);
            h[1] = __floats2half2_rn(v0.z, v0.w);
            h[2] = __floats2half2_rn(v1.x, v1.y);
            h[3] = __floats2half2_rn(v1.z, v1.w);
            *reinterpret_cast<uint4*>(dst + p * 256) = *reinterpret_cast<uint4*>(h);
        }
    }
    // CLS: 128 imgs x 192 float4 = 24576 items on first 96 blocks
    if (blockIdx.x < 96) {
        const int i   = blockIdx.x * 256 + threadIdx.x;
        const int img = i / 192, n4 = i - img * 192;
        reinterpret_cast<float4*>(out + (size_t)img * 197 * NDIM)[n4] =
            reinterpret_cast<const float4*>(cls)[n4];
    }
}

// ---------------- main GEMM (R9 exact) ----------------
__global__ __launch_bounds__(256, 1) void vit_gemm(
    const float* __restrict__ bias,
    float* __restrict__ out)
{
    extern __shared__ __align__(16) char smc[];

    const int tid  = threadIdx.x;
    const int lane = tid & 31;
    const int warp = tid >> 5;          // 0..7
    const int wm   = warp & 1;          // 2 m-positions of 64
    const int wn   = warp >> 1;         // 4 n-positions of 64
    const int g    = lane >> 2;         // 0..7
    const int tg   = lane & 3;          // 0..3

    const int bm = blockIdx.y * BM;
    const int bn = blockIdx.x * BN;

    // ---------------- loader mapping (quarter-warp = one 128B row) ----------------
    const int lq = lane >> 3;           // 0..3 row slot
    const int lc = lane & 7;            // 0..7 chunk
    const uint32_t x_even = (uint32_t)((lc ^ lq) << 4);
    const uint32_t x_odd  = (uint32_t)((lc ^ (lq + 4)) << 4);

    const __half* asrc = A_pre + (size_t)(bm + 16 * warp + lq) * KDIM + lc * 8;
    const __half* bsrc = W_h   + (size_t)(bn + 32 * warp + lq) * KDIM + lc * 8;
    const uint32_t sts_a0 = (uint32_t)(16 * warp + lq) * AROW_B;
    const uint32_t sts_b0 = (uint32_t)ASTAGE_B + (uint32_t)(32 * warp + lq) * AROW_B;

    const uint32_t sbase = (uint32_t)__cvta_generic_to_shared(smc);

    auto load_tile = [&](int it) {
        const int st = it - (it / NSTG) * NSTG;
        const int k0 = it * BK;
        const uint32_t sb0 = sbase + (uint32_t)st * STAGE_BYTES;
        #pragma unroll
        for (int i = 0; i < 4; ++i)
            cp16(sb0 + sts_a0 + i * 512u + ((i & 1) ? x_odd : x_even),
                 asrc + (size_t)i * (4 * KDIM) + k0);
        #pragma unroll
        for (int i = 0; i < 8; ++i)
            cp16(sb0 + sts_b0 + i * 512u + ((i & 1) ? x_odd : x_even),
                 bsrc + (size_t)i * (4 * KDIM) + k0);
    };

    float acc[4][8][4];
    #pragma unroll
    for (int mt = 0; mt < 4; ++mt)
        #pragma unroll
        for (int nt = 0; nt < 8; ++nt)
            #pragma unroll
            for (int r = 0; r < 4; ++r) acc[mt][nt][r] = 0.f;

    load_tile(0); cp_commit();
    load_tile(1); cp_commit();

    // ---------------- ldmatrix lane constants ----------------
    const int a_sub = (lane & 7) + ((lane >> 3) & 1) * 8;
    const int chA   = (lane >> 4) & 1;
    const int b_sub = (lane & 7) + ((lane >> 4) & 1) * 8;
    const int chB   = (lane >> 3) & 1;
    const uint32_t lx = (uint32_t)(lane & 7);
    const uint32_t aBase = (uint32_t)(wm * 64 + a_sub) * AROW_B;
    const uint32_t bBase = (uint32_t)ASTAGE_B + (uint32_t)(wn * 64 + b_sub) * AROW_B;

    for (int it = 0; it < NITER; ++it) {
        if (it == NITER - 1) cp_wait<0>(); else cp_wait<1>();
        __syncthreads();

        const int st = it - (it / NSTG) * NSTG;
        const uint32_t stg = sbase + (uint32_t)st * STAGE_BYTES;

        #pragma unroll
        for (int ks = 0; ks < 4; ++ks) {
            uint32_t af[4][4], bf[4][4];
            const uint32_t ach = ((uint32_t)(2 * ks + chA) ^ lx) << 4;
            const uint32_t bch = ((uint32_t)(2 * ks + chB) ^ lx) << 4;
            #pragma unroll
            for (int mt = 0; mt < 4; ++mt)
                ldsm4(af[mt], stg + aBase + mt * 2048u + ach);
            #pragma unroll
            for (int p = 0; p < 4; ++p)
                ldsm4(bf[p], stg + bBase + p * 2048u + bch);

            if (ks == 0 && it + 2 < NITER) { load_tile(it + 2); cp_commit(); }

            #pragma unroll
            for (int mt = 0; mt < 4; ++mt)
                #pragma unroll
                for (int nt = 0; nt < 8; ++nt)
                    mma_f16(acc[mt][nt], af[mt], &bf[nt >> 1][(nt & 1) * 2]);
        }
    }

    // ---------------- epilogue: bias + scatter ----------------
    float bv[8][2];
    #pragma unroll
    for (int nt = 0; nt < 8; ++nt) {
        const int col = bn + wn * 64 + nt * 8 + tg * 2;
        bv[nt][0] = bias[col];
        bv[nt][1] = bias[col + 1];
    }

    #pragma unroll
    for (int mt = 0; mt < 4; ++mt) {
        #pragma unroll
        for (int rh = 0; rh < 2; ++rh) {
            const int m     = bm + wm * 64 + mt * 16 + rh * 8 + g;
            const int img   = m / NPATCH;
            const int patch = m - img * NPATCH;
            float* orow = out + ((size_t)img * 197 + patch + 1) * NDIM;
            #pragma unroll
            for (int nt = 0; nt < 8; ++nt) {
                const int col = bn + wn * 64 + nt * 8 + tg * 2;
                float2 v;
                v.x = acc[mt][nt][rh * 2 + 0] + bv[nt][0];
                v.y = acc[mt][nt][rh * 2 + 1] + bv[nt][1];
                *reinterpret_cast<float2*>(orow + col) = v;
            }
        }
    }
}

extern "C" void kernel_launch(void* const* d_in, const int* in_sizes, int n_in,
                              void* d_out, int out_size) {
    const float* images = (const float*)d_in[0];
    const float* W      = (const float*)d_in[1];
    const float* b      = (const float*)d_in[2];
    const float* cls    = (const float*)d_in[3];
    float* out          = (float*)d_out;

    cudaFuncSetAttribute(vit_gemm, cudaFuncAttributeMaxDynamicSharedMemorySize, SMEM_BYTES);

    prepass<<<PRE_BLOCKS, 256>>>(images, W, cls, out);
    dim3 grid(NDIM / BN, MTOT / BM);   // (3, 196): the 3 A-sharers run concurrently (L2 reuse)
    vit_gemm<<<grid, 256, SMEM_BYTES>>>(b, out);
}